// round 14
// baseline (speedup 1.0000x reference)
#include <cuda_runtime.h>
#include <cuda_bf16.h>

// Problem constants (fixed by the reference).
#define NROWS   2000000
#define DIM     128
#define NCLS    1000
#define DECAY   0.3f

// One wave: 148 CTAs x 1024 threads. CHUNK divisible by 4 for int4 loads.
// 148 * 13516 = 2000368 >= NROWS; last CTA tail (13148) is also divisible by 4.
#define NBLK    148
#define CHUNK   13516
#define THREADS 1024

// Classes whose rows get L2-prefetched during the (DRAM-idle) prologue.
// Warps process classes wid, wid+32, ... so classes 0..63 are the first two
// classes of every warp = consumed in the first microseconds of phase 4.
#define PF_CLS  64

// Scratch accumulators (allocation-free: __device__ globals).
// Zero at module load; finalize_kernel restores zeros after every call, so the
// zero-invariant holds across the correctness run and all graph replays.
__device__ __align__(16) float g_sums[NCLS * DIM];
__device__ float    g_counts[NCLS];
__device__ unsigned g_present[NCLS];

// Fire-and-forget L2 prefetch of one 512-byte x row (4 x 128B lines).
// No destination register -> no scoreboard interaction.
__device__ __forceinline__ void pf_row(const float* x, int row) {
    const char* p = (const char*)x + (size_t)row * 512;
    asm volatile("prefetch.global.L2 [%0];"     :: "l"(p));
    asm volatile("prefetch.global.L2 [%0];"     :: "l"(p + 128));
    asm volatile("prefetch.global.L2 [%0];"     :: "l"(p + 256));
    asm volatile("prefetch.global.L2 [%0];"     :: "l"(p + 384));
}

__global__ __launch_bounds__(THREADS, 1) void accum_kernel(
    const float* __restrict__ x,
    const int* __restrict__ y,
    const int* __restrict__ mask)   // bool exported as int32
{
    __shared__ unsigned       s_hist[1024];   // padded to 1024 for the scan
    __shared__ unsigned       s_off[1024];
    __shared__ unsigned       s_cur[NCLS];
    __shared__ unsigned       s_warp[32];
    __shared__ unsigned short s_bin[CHUNK];   // chunk-local row offsets (masked rows only)

    const int tid    = threadIdx.x;
    const int row0   = blockIdx.x * CHUNK;
    const int rowEnd = min(row0 + CHUNK, NROWS);
    const int nvec   = (rowEnd - row0) >> 2;  // always exact (all tails %4==0)
    const unsigned lane = tid & 31;
    const unsigned wid  = tid >> 5;

    const int4* __restrict__ y4 = (const int4*)(y + row0);
    const int4* __restrict__ m4 = (const int4*)(mask + row0);

    // ---- Phase 1: full (unmasked) class histogram of this chunk (int4 loads),
    //      plus L2 prefetch of rows belonging to the first-scheduled classes —
    //      this uses the otherwise DRAM-idle prologue window. ----
    s_hist[tid] = 0u;
    __syncthreads();
    for (int i = tid; i < nvec; i += THREADS) {
        int4 c = y4[i];
        atomicAdd(&s_hist[c.x], 1u);
        atomicAdd(&s_hist[c.y], 1u);
        atomicAdd(&s_hist[c.z], 1u);
        atomicAdd(&s_hist[c.w], 1u);
        int b = row0 + (i << 2);
        if (c.x < PF_CLS) pf_row(x, b);
        if (c.y < PF_CLS) pf_row(x, b + 1);
        if (c.z < PF_CLS) pf_row(x, b + 2);
        if (c.w < PF_CLS) pf_row(x, b + 3);
    }
    __syncthreads();

    // ---- Phase 2: exclusive scan over 1024 entries (1 per thread) ----
    unsigned v   = s_hist[tid];
    unsigned inc = v;
    #pragma unroll
    for (int o = 1; o < 32; o <<= 1) {
        unsigned n = __shfl_up_sync(0xFFFFFFFFu, inc, o);
        if (lane >= (unsigned)o) inc += n;
    }
    if (lane == 31) s_warp[wid] = inc;
    __syncthreads();
    if (wid == 0) {
        unsigned wv = s_warp[lane];
        #pragma unroll
        for (int o = 1; o < 32; o <<= 1) {
            unsigned n = __shfl_up_sync(0xFFFFFFFFu, wv, o);
            if (lane >= (unsigned)o) wv += n;
        }
        s_warp[lane] = wv;
    }
    __syncthreads();
    unsigned excl = inc - v + (wid ? s_warp[wid - 1] : 0u);
    s_off[tid] = excl;
    if (tid < NCLS) s_cur[tid] = excl;
    __syncthreads();

    // ---- Phase 3: scatter MASKED row offsets into class bins (y is L2-hot) ----
    for (int i = tid; i < nvec; i += THREADS) {
        int4 c = y4[i];
        int4 m = m4[i];
        int  b = i << 2;
        if (m.x) { unsigned p = atomicAdd(&s_cur[c.x], 1u); s_bin[p] = (unsigned short)(b);     }
        if (m.y) { unsigned p = atomicAdd(&s_cur[c.y], 1u); s_bin[p] = (unsigned short)(b + 1); }
        if (m.z) { unsigned p = atomicAdd(&s_cur[c.z], 1u); s_bin[p] = (unsigned short)(b + 2); }
        if (m.w) { unsigned p = atomicAdd(&s_cur[c.w], 1u); s_bin[p] = (unsigned short)(b + 3); }
    }
    __syncthreads();

    // ---- Phase 4: one warp per class (strided): uniform clamped unroll-8
    //      (8 independent 512B loads in flight per warp), 2 alternating
    //      accumulators, then one red.global.add.v4.f32 per (CTA, class). ----
    const float4* __restrict__ x4 = (const float4*)x;
    for (int c = (int)wid; c < NCLS; c += 32) {
        unsigned h    = s_hist[c];          // unmasked presence
        unsigned base = s_off[c];
        unsigned k    = s_cur[c] - base;    // masked count

        if (lane == 0) {
            if (h) g_present[c] = 1u;       // racing identical stores: fine
            if (k) atomicAdd(&g_counts[c], (float)k);
        }
        if (!k) continue;

        float4 a0 = make_float4(0.f, 0.f, 0.f, 0.f);
        float4 a1 = make_float4(0.f, 0.f, 0.f, 0.f);

        unsigned klast = k - 1;
        for (unsigned j = 0; j < k; j += 8) {
            float4 vv[8];
            float  w[8];
            #pragma unroll
            for (int t = 0; t < 8; t++) {
                unsigned ji = j + (unsigned)t;
                unsigned jc = min(ji, klast);
                w[t] = (ji <= klast) ? 1.f : 0.f;
                int ri = row0 + (int)s_bin[base + jc];
                vv[t] = __ldcs(&x4[(size_t)ri * 32 + lane]);
            }
            #pragma unroll
            for (int t = 0; t < 8; t += 2) {
                a0.x += vv[t].x * w[t];     a0.y += vv[t].y * w[t];
                a0.z += vv[t].z * w[t];     a0.w += vv[t].w * w[t];
                a1.x += vv[t+1].x * w[t+1]; a1.y += vv[t+1].y * w[t+1];
                a1.z += vv[t+1].z * w[t+1]; a1.w += vv[t+1].w * w[t+1];
            }
        }
        a0.x += a1.x; a0.y += a1.y; a0.z += a1.z; a0.w += a1.w;

        float* dst = &g_sums[c * DIM + lane * 4];
        asm volatile("red.global.add.v4.f32 [%0], {%1, %2, %3, %4};"
                     :: "l"(dst), "f"(a0.x), "f"(a0.y), "f"(a0.z), "f"(a0.w)
                     : "memory");
    }
}

// One thread per float4 (32000 threads). Branchless: all input loads issued
// independently (MLP 4), select at the end.
__global__ void finalize_kernel(const float4* __restrict__ centroids,
                                float4* __restrict__ out)
{
    int idx = blockIdx.x * blockDim.x + threadIdx.x;   // float4 index
    if (idx >= NCLS * DIM / 4) return;
    int c = idx >> 5;                                   // 32 float4 per class row

    float4   cent = centroids[idx];
    float4   s    = ((const float4*)g_sums)[idx];
    float    cnt  = g_counts[c];
    unsigned pres = g_present[c];

    float invn = DECAY / fmaxf(cnt, 1.0f);
    float keep = 1.0f - DECAY;
    float4 ema;
    ema.x = s.x * invn + keep * cent.x;
    ema.y = s.y * invn + keep * cent.y;
    ema.z = s.z * invn + keep * cent.z;
    ema.w = s.w * invn + keep * cent.w;

    out[idx] = pres ? ema : cent;

    // Restore the zero-invariant for the next call / graph replay.
    ((float4*)g_sums)[idx] = make_float4(0.f, 0.f, 0.f, 0.f);
    if (idx < NCLS) { g_counts[idx] = 0.0f; g_present[idx] = 0u; }
}

extern "C" void kernel_launch(void* const* d_in, const int* in_sizes, int n_in,
                              void* d_out, int out_size)
{
    const float* x         = (const float*)d_in[0];
    const int*   y         = (const int*)d_in[1];
    const int*   mask      = (const int*)d_in[2];
    const float* centroids = (const float*)d_in[3];
    float*       out       = (float*)d_out;

    accum_kernel<<<NBLK, THREADS>>>(x, y, mask);
    finalize_kernel<<<(NCLS * DIM / 4 + 255) / 256, 256>>>(
        (const float4*)centroids, (float4*)out);
}

// round 15
// speedup vs baseline: 1.0090x; 1.0090x over previous
#include <cuda_runtime.h>
#include <cuda_bf16.h>

// Problem constants (fixed by the reference).
#define NROWS   2000000
#define DIM     128
#define NCLS    1000
#define DECAY   0.3f

// One wave: 148 CTAs x 1024 threads. CHUNK divisible by 4 for int4 loads.
// 148 * 13516 = 2000368 >= NROWS; last CTA tail (13148) is also divisible by 4.
#define NBLK    148
#define CHUNK   13516
#define THREADS 1024

// Classes whose rows get L2-prefetched during the (DRAM-idle) prologue.
// Warps process classes wid, wid+32, ... so classes 0..63 are the first two
// classes of every warp = consumed in the first microseconds of phase 4.
#define PF_CLS  64

// Scratch accumulators (allocation-free: __device__ globals).
// Zero at module load; finalize_kernel restores zeros after every call, so the
// zero-invariant holds across the correctness run and all graph replays.
__device__ __align__(16) float g_sums[NCLS * DIM];
__device__ float    g_counts[NCLS];
__device__ unsigned g_present[NCLS];

// Fire-and-forget L2 prefetch of one 512-byte x row (4 x 128B lines).
// No destination register -> no scoreboard interaction.
__device__ __forceinline__ void pf_row(const float* x, int row) {
    const char* p = (const char*)x + (size_t)row * 512;
    asm volatile("prefetch.global.L2 [%0];"     :: "l"(p));
    asm volatile("prefetch.global.L2 [%0];"     :: "l"(p + 128));
    asm volatile("prefetch.global.L2 [%0];"     :: "l"(p + 256));
    asm volatile("prefetch.global.L2 [%0];"     :: "l"(p + 384));
}

__global__ __launch_bounds__(THREADS, 1) void accum_kernel(
    const float* __restrict__ x,
    const int* __restrict__ y,
    const int* __restrict__ mask)   // bool exported as int32
{
    __shared__ unsigned       s_hist[1024];   // padded to 1024 for the scan
    __shared__ unsigned       s_off[1024];
    __shared__ unsigned       s_cur[NCLS];
    __shared__ unsigned       s_warp[32];
    __shared__ unsigned short s_bin[CHUNK];   // chunk-local row offsets (masked rows only)

    const int tid    = threadIdx.x;
    const int row0   = blockIdx.x * CHUNK;
    const int rowEnd = min(row0 + CHUNK, NROWS);
    const int nvec   = (rowEnd - row0) >> 2;  // always exact (all tails %4==0)
    const unsigned lane = tid & 31;
    const unsigned wid  = tid >> 5;

    const int4* __restrict__ y4 = (const int4*)(y + row0);
    const int4* __restrict__ m4 = (const int4*)(mask + row0);

    // ---- Phase 1: full (unmasked) class histogram of this chunk (int4 loads),
    //      plus L2 prefetch of rows belonging to the first-scheduled classes —
    //      this uses the otherwise DRAM-idle prologue window. ----
    s_hist[tid] = 0u;
    __syncthreads();
    for (int i = tid; i < nvec; i += THREADS) {
        int4 c = y4[i];
        atomicAdd(&s_hist[c.x], 1u);
        atomicAdd(&s_hist[c.y], 1u);
        atomicAdd(&s_hist[c.z], 1u);
        atomicAdd(&s_hist[c.w], 1u);
        int b = row0 + (i << 2);
        if (c.x < PF_CLS) pf_row(x, b);
        if (c.y < PF_CLS) pf_row(x, b + 1);
        if (c.z < PF_CLS) pf_row(x, b + 2);
        if (c.w < PF_CLS) pf_row(x, b + 3);
    }
    __syncthreads();

    // ---- Phase 2: exclusive scan over 1024 entries (1 per thread) ----
    unsigned v   = s_hist[tid];
    unsigned inc = v;
    #pragma unroll
    for (int o = 1; o < 32; o <<= 1) {
        unsigned n = __shfl_up_sync(0xFFFFFFFFu, inc, o);
        if (lane >= (unsigned)o) inc += n;
    }
    if (lane == 31) s_warp[wid] = inc;
    __syncthreads();
    if (wid == 0) {
        unsigned wv = s_warp[lane];
        #pragma unroll
        for (int o = 1; o < 32; o <<= 1) {
            unsigned n = __shfl_up_sync(0xFFFFFFFFu, wv, o);
            if (lane >= (unsigned)o) wv += n;
        }
        s_warp[lane] = wv;
    }
    __syncthreads();
    unsigned excl = inc - v + (wid ? s_warp[wid - 1] : 0u);
    s_off[tid] = excl;
    if (tid < NCLS) s_cur[tid] = excl;
    __syncthreads();

    // ---- Phase 3: scatter MASKED row offsets into class bins (y is L2-hot) ----
    for (int i = tid; i < nvec; i += THREADS) {
        int4 c = y4[i];
        int4 m = m4[i];
        int  b = i << 2;
        if (m.x) { unsigned p = atomicAdd(&s_cur[c.x], 1u); s_bin[p] = (unsigned short)(b);     }
        if (m.y) { unsigned p = atomicAdd(&s_cur[c.y], 1u); s_bin[p] = (unsigned short)(b + 1); }
        if (m.z) { unsigned p = atomicAdd(&s_cur[c.z], 1u); s_bin[p] = (unsigned short)(b + 2); }
        if (m.w) { unsigned p = atomicAdd(&s_cur[c.w], 1u); s_bin[p] = (unsigned short)(b + 3); }
    }
    __syncthreads();

    // ---- Phase 4: one warp per class (strided): uniform clamped unroll-8
    //      (8 independent 512B loads in flight per warp), 2 alternating
    //      accumulators, then one red.global.add.v4.f32 per (CTA, class). ----
    const float4* __restrict__ x4 = (const float4*)x;
    for (int c = (int)wid; c < NCLS; c += 32) {
        unsigned h    = s_hist[c];          // unmasked presence
        unsigned base = s_off[c];
        unsigned k    = s_cur[c] - base;    // masked count

        if (lane == 0) {
            if (h) g_present[c] = 1u;       // racing identical stores: fine
            if (k) atomicAdd(&g_counts[c], (float)k);
        }
        if (!k) continue;

        float4 a0 = make_float4(0.f, 0.f, 0.f, 0.f);
        float4 a1 = make_float4(0.f, 0.f, 0.f, 0.f);

        unsigned klast = k - 1;
        for (unsigned j = 0; j < k; j += 8) {
            float4 vv[8];
            float  w[8];
            #pragma unroll
            for (int t = 0; t < 8; t++) {
                unsigned ji = j + (unsigned)t;
                unsigned jc = min(ji, klast);
                w[t] = (ji <= klast) ? 1.f : 0.f;
                int ri = row0 + (int)s_bin[base + jc];
                vv[t] = __ldcs(&x4[(size_t)ri * 32 + lane]);
            }
            #pragma unroll
            for (int t = 0; t < 8; t += 2) {
                a0.x += vv[t].x * w[t];     a0.y += vv[t].y * w[t];
                a0.z += vv[t].z * w[t];     a0.w += vv[t].w * w[t];
                a1.x += vv[t+1].x * w[t+1]; a1.y += vv[t+1].y * w[t+1];
                a1.z += vv[t+1].z * w[t+1]; a1.w += vv[t+1].w * w[t+1];
            }
        }
        a0.x += a1.x; a0.y += a1.y; a0.z += a1.z; a0.w += a1.w;

        float* dst = &g_sums[c * DIM + lane * 4];
        asm volatile("red.global.add.v4.f32 [%0], {%1, %2, %3, %4};"
                     :: "l"(dst), "f"(a0.x), "f"(a0.y), "f"(a0.z), "f"(a0.w)
                     : "memory");
    }
}

// One thread per float4 (32000 threads). Branchless: all input loads issued
// independently (MLP 4), select at the end.
__global__ void finalize_kernel(const float4* __restrict__ centroids,
                                float4* __restrict__ out)
{
    int idx = blockIdx.x * blockDim.x + threadIdx.x;   // float4 index
    if (idx >= NCLS * DIM / 4) return;
    int c = idx >> 5;                                   // 32 float4 per class row

    float4   cent = centroids[idx];
    float4   s    = ((const float4*)g_sums)[idx];
    float    cnt  = g_counts[c];
    unsigned pres = g_present[c];

    float invn = DECAY / fmaxf(cnt, 1.0f);
    float keep = 1.0f - DECAY;
    float4 ema;
    ema.x = s.x * invn + keep * cent.x;
    ema.y = s.y * invn + keep * cent.y;
    ema.z = s.z * invn + keep * cent.z;
    ema.w = s.w * invn + keep * cent.w;

    out[idx] = pres ? ema : cent;

    // Restore the zero-invariant for the next call / graph replay.
    ((float4*)g_sums)[idx] = make_float4(0.f, 0.f, 0.f, 0.f);
    if (idx < NCLS) { g_counts[idx] = 0.0f; g_present[idx] = 0u; }
}

extern "C" void kernel_launch(void* const* d_in, const int* in_sizes, int n_in,
                              void* d_out, int out_size)
{
    const float* x         = (const float*)d_in[0];
    const int*   y         = (const int*)d_in[1];
    const int*   mask      = (const int*)d_in[2];
    const float* centroids = (const float*)d_in[3];
    float*       out       = (float*)d_out;

    accum_kernel<<<NBLK, THREADS>>>(x, y, mask);
    finalize_kernel<<<(NCLS * DIM / 4 + 255) / 256, 256>>>(
        (const float4*)centroids, (float4*)out);
}

// round 16
// speedup vs baseline: 1.0196x; 1.0106x over previous
#include <cuda_runtime.h>
#include <cuda_bf16.h>

// Problem constants (fixed by the reference).
#define NROWS   2000000
#define DIM     128
#define NCLS    1000
#define DECAY   0.3f

// One wave: 148 CTAs x 1024 threads. CHUNK divisible by 4 for int4 loads.
// 148 * 13516 = 2000368 >= NROWS; last CTA tail (13148) is also divisible by 4.
#define NBLK    148
#define CHUNK   13516
#define THREADS 1024

// Scratch accumulators (allocation-free: __device__ globals).
// Zero at module load; finalize_kernel restores zeros after every call, so the
// zero-invariant holds across the correctness run and all graph replays.
__device__ __align__(16) float g_sums[NCLS * DIM];
__device__ float    g_counts[NCLS];
__device__ unsigned g_present[NCLS];

__global__ __launch_bounds__(THREADS, 1) void accum_kernel(
    const float* __restrict__ x,
    const int* __restrict__ y,
    const int* __restrict__ mask)   // bool exported as int32
{
    __shared__ unsigned       s_hist[1024];   // padded to 1024 for the scan
    __shared__ unsigned       s_off[1024];
    __shared__ unsigned       s_cur[NCLS];
    __shared__ unsigned       s_warp[32];
    __shared__ unsigned short s_bin[CHUNK];   // chunk-local row offsets (masked rows only)

    const int tid    = threadIdx.x;
    const int row0   = blockIdx.x * CHUNK;
    const int rowEnd = min(row0 + CHUNK, NROWS);
    const int nvec   = (rowEnd - row0) >> 2;  // always exact (all tails %4==0)
    const unsigned lane = tid & 31;
    const unsigned wid  = tid >> 5;

    const int4* __restrict__ y4 = (const int4*)(y + row0);
    const int4* __restrict__ m4 = (const int4*)(mask + row0);

    // ---- Phase 1: full (unmasked) class histogram of this chunk (int4 loads) ----
    s_hist[tid] = 0u;
    __syncthreads();
    for (int i = tid; i < nvec; i += THREADS) {
        int4 c = y4[i];
        atomicAdd(&s_hist[c.x], 1u);
        atomicAdd(&s_hist[c.y], 1u);
        atomicAdd(&s_hist[c.z], 1u);
        atomicAdd(&s_hist[c.w], 1u);
    }
    __syncthreads();

    // ---- Phase 2: exclusive scan over 1024 entries (1 per thread) ----
    unsigned v   = s_hist[tid];
    unsigned inc = v;
    #pragma unroll
    for (int o = 1; o < 32; o <<= 1) {
        unsigned n = __shfl_up_sync(0xFFFFFFFFu, inc, o);
        if (lane >= (unsigned)o) inc += n;
    }
    if (lane == 31) s_warp[wid] = inc;
    __syncthreads();
    if (wid == 0) {
        unsigned wv = s_warp[lane];
        #pragma unroll
        for (int o = 1; o < 32; o <<= 1) {
            unsigned n = __shfl_up_sync(0xFFFFFFFFu, wv, o);
            if (lane >= (unsigned)o) wv += n;
        }
        s_warp[lane] = wv;
    }
    __syncthreads();
    unsigned excl = inc - v + (wid ? s_warp[wid - 1] : 0u);
    s_off[tid] = excl;
    if (tid < NCLS) s_cur[tid] = excl;
    __syncthreads();

    // ---- Phase 3: scatter MASKED row offsets into class bins (y is L2-hot) ----
    for (int i = tid; i < nvec; i += THREADS) {
        int4 c = y4[i];
        int4 m = m4[i];
        int  b = i << 2;
        if (m.x) { unsigned p = atomicAdd(&s_cur[c.x], 1u); s_bin[p] = (unsigned short)(b);     }
        if (m.y) { unsigned p = atomicAdd(&s_cur[c.y], 1u); s_bin[p] = (unsigned short)(b + 1); }
        if (m.z) { unsigned p = atomicAdd(&s_cur[c.z], 1u); s_bin[p] = (unsigned short)(b + 2); }
        if (m.w) { unsigned p = atomicAdd(&s_cur[c.w], 1u); s_bin[p] = (unsigned short)(b + 3); }
    }
    __syncthreads();

    // ---- Phase 4: one warp per class (strided). Pure unroll-8 main loop
    //      (no clamps, no weight FMAs) + clamped-4 tail; then one
    //      red.global.add.v4.f32 per (CTA, class). ----
    const float4* __restrict__ x4 = (const float4*)x;
    for (int c = (int)wid; c < NCLS; c += 32) {
        unsigned h    = s_hist[c];          // unmasked presence
        unsigned base = s_off[c];
        unsigned k    = s_cur[c] - base;    // masked count

        if (lane == 0) {
            if (h) g_present[c] = 1u;       // racing identical stores: fine
            if (k) atomicAdd(&g_counts[c], (float)k);
        }
        if (!k) continue;

        float4 a0 = make_float4(0.f, 0.f, 0.f, 0.f);
        float4 a1 = make_float4(0.f, 0.f, 0.f, 0.f);

        unsigned j = 0;
        // Main loop: 8 independent 512B loads in flight, zero clamp overhead.
        for (; j + 8 <= k; j += 8) {
            float4 vv[8];
            #pragma unroll
            for (int t = 0; t < 8; t++) {
                int ri = row0 + (int)s_bin[base + j + (unsigned)t];
                vv[t] = __ldcs(&x4[(size_t)ri * 32 + lane]);
            }
            #pragma unroll
            for (int t = 0; t < 8; t += 2) {
                a0.x += vv[t].x;   a0.y += vv[t].y;   a0.z += vv[t].z;   a0.w += vv[t].w;
                a1.x += vv[t+1].x; a1.y += vv[t+1].y; a1.z += vv[t+1].z; a1.w += vv[t+1].w;
            }
        }
        // Clamped-4 tail (covers remainder 1..7 in one or two batches, MLP-4).
        if (j < k) {
            unsigned klast = k - 1;
            for (; j < k; j += 4) {
                unsigned j1 = min(j + 1, klast);
                unsigned j2 = min(j + 2, klast);
                unsigned j3 = min(j + 3, klast);
                float w1 = (j + 1 <= klast) ? 1.f : 0.f;
                float w2 = (j + 2 <= klast) ? 1.f : 0.f;
                float w3 = (j + 3 <= klast) ? 1.f : 0.f;
                int i0 = row0 + (int)s_bin[base + j];
                int i1 = row0 + (int)s_bin[base + j1];
                int i2 = row0 + (int)s_bin[base + j2];
                int i3 = row0 + (int)s_bin[base + j3];
                float4 v0 = __ldcs(&x4[(size_t)i0 * 32 + lane]);
                float4 v1 = __ldcs(&x4[(size_t)i1 * 32 + lane]);
                float4 v2 = __ldcs(&x4[(size_t)i2 * 32 + lane]);
                float4 v3 = __ldcs(&x4[(size_t)i3 * 32 + lane]);
                a0.x += v0.x;      a0.y += v0.y;      a0.z += v0.z;      a0.w += v0.w;
                a1.x += v1.x * w1; a1.y += v1.y * w1; a1.z += v1.z * w1; a1.w += v1.w * w1;
                a0.x += v2.x * w2; a0.y += v2.y * w2; a0.z += v2.z * w2; a0.w += v2.w * w2;
                a1.x += v3.x * w3; a1.y += v3.y * w3; a1.z += v3.z * w3; a1.w += v3.w * w3;
            }
        }
        a0.x += a1.x; a0.y += a1.y; a0.z += a1.z; a0.w += a1.w;

        float* dst = &g_sums[c * DIM + lane * 4];
        asm volatile("red.global.add.v4.f32 [%0], {%1, %2, %3, %4};"
                     :: "l"(dst), "f"(a0.x), "f"(a0.y), "f"(a0.z), "f"(a0.w)
                     : "memory");
    }
}

// One thread per float4 (32000 threads). Branchless: all input loads issued
// independently (MLP 4), select at the end.
__global__ void finalize_kernel(const float4* __restrict__ centroids,
                                float4* __restrict__ out)
{
    int idx = blockIdx.x * blockDim.x + threadIdx.x;   // float4 index
    if (idx >= NCLS * DIM / 4) return;
    int c = idx >> 5;                                   // 32 float4 per class row

    float4   cent = centroids[idx];
    float4   s    = ((const float4*)g_sums)[idx];
    float    cnt  = g_counts[c];
    unsigned pres = g_present[c];

    float invn = DECAY / fmaxf(cnt, 1.0f);
    float keep = 1.0f - DECAY;
    float4 ema;
    ema.x = s.x * invn + keep * cent.x;
    ema.y = s.y * invn + keep * cent.y;
    ema.z = s.z * invn + keep * cent.z;
    ema.w = s.w * invn + keep * cent.w;

    out[idx] = pres ? ema : cent;

    // Restore the zero-invariant for the next call / graph replay.
    ((float4*)g_sums)[idx] = make_float4(0.f, 0.f, 0.f, 0.f);
    if (idx < NCLS) { g_counts[idx] = 0.0f; g_present[idx] = 0u; }
}

extern "C" void kernel_launch(void* const* d_in, const int* in_sizes, int n_in,
                              void* d_out, int out_size)
{
    const float* x         = (const float*)d_in[0];
    const int*   y         = (const int*)d_in[1];
    const int*   mask      = (const int*)d_in[2];
    const float* centroids = (const float*)d_in[3];
    float*       out       = (float*)d_out;

    accum_kernel<<<NBLK, THREADS>>>(x, y, mask);
    finalize_kernel<<<(NCLS * DIM / 4 + 255) / 256, 256>>>(
        (const float4*)centroids, (float4*)out);
}

// round 17
// speedup vs baseline: 1.0648x; 1.0443x over previous
#include <cuda_runtime.h>
#include <cuda_bf16.h>

// Problem constants (fixed by the reference).
#define NROWS   2000000
#define DIM     128
#define NCLS    1000
#define DECAY   0.3f

// One wave: 148 CTAs x 1024 threads. CHUNK divisible by 4 for int4 loads.
// 148 * 13516 = 2000368 >= NROWS; last CTA tail (13148) is also divisible by 4.
#define NBLK    148
#define CHUNK   13516
#define THREADS 1024

// Scratch accumulators (allocation-free: __device__ globals).
// Zero at module load; finalize_kernel restores zeros after every call, so the
// zero-invariant holds across the correctness run and all graph replays.
__device__ __align__(16) float g_sums[NCLS * DIM];
__device__ float    g_counts[NCLS];
__device__ unsigned g_present[NCLS];

__global__ __launch_bounds__(THREADS, 1) void accum_kernel(
    const float* __restrict__ x,
    const int* __restrict__ y,
    const int* __restrict__ mask)   // bool exported as int32
{
    __shared__ unsigned       s_hist[1024];   // padded to 1024 for the scan
    __shared__ unsigned       s_off[1024];
    __shared__ unsigned       s_cur[NCLS];
    __shared__ unsigned       s_warp[32];
    __shared__ unsigned short s_bin[CHUNK];   // chunk-local row offsets (masked rows only)

    const int tid    = threadIdx.x;
    const int row0   = blockIdx.x * CHUNK;
    const int rowEnd = min(row0 + CHUNK, NROWS);
    const int nvec   = (rowEnd - row0) >> 2;  // always exact (all tails %4==0)
    const unsigned lane = tid & 31;
    const unsigned wid  = tid >> 5;

    const int4* __restrict__ y4 = (const int4*)(y + row0);
    const int4* __restrict__ m4 = (const int4*)(mask + row0);

    // ---- Phase 1: full (unmasked) class histogram of this chunk (int4 loads) ----
    s_hist[tid] = 0u;
    __syncthreads();
    for (int i = tid; i < nvec; i += THREADS) {
        int4 c = y4[i];
        atomicAdd(&s_hist[c.x], 1u);
        atomicAdd(&s_hist[c.y], 1u);
        atomicAdd(&s_hist[c.z], 1u);
        atomicAdd(&s_hist[c.w], 1u);
    }
    __syncthreads();

    // ---- Phase 2: exclusive scan over 1024 entries (1 per thread) ----
    unsigned v   = s_hist[tid];
    unsigned inc = v;
    #pragma unroll
    for (int o = 1; o < 32; o <<= 1) {
        unsigned n = __shfl_up_sync(0xFFFFFFFFu, inc, o);
        if (lane >= (unsigned)o) inc += n;
    }
    if (lane == 31) s_warp[wid] = inc;
    __syncthreads();
    if (wid == 0) {
        unsigned wv = s_warp[lane];
        #pragma unroll
        for (int o = 1; o < 32; o <<= 1) {
            unsigned n = __shfl_up_sync(0xFFFFFFFFu, wv, o);
            if (lane >= (unsigned)o) wv += n;
        }
        s_warp[lane] = wv;
    }
    __syncthreads();
    unsigned excl = inc - v + (wid ? s_warp[wid - 1] : 0u);
    s_off[tid] = excl;
    if (tid < NCLS) s_cur[tid] = excl;
    __syncthreads();

    // ---- Phase 3: scatter MASKED row offsets into class bins (y is L2-hot) ----
    for (int i = tid; i < nvec; i += THREADS) {
        int4 c = y4[i];
        int4 m = m4[i];
        int  b = i << 2;
        if (m.x) { unsigned p = atomicAdd(&s_cur[c.x], 1u); s_bin[p] = (unsigned short)(b);     }
        if (m.y) { unsigned p = atomicAdd(&s_cur[c.y], 1u); s_bin[p] = (unsigned short)(b + 1); }
        if (m.z) { unsigned p = atomicAdd(&s_cur[c.z], 1u); s_bin[p] = (unsigned short)(b + 2); }
        if (m.w) { unsigned p = atomicAdd(&s_cur[c.w], 1u); s_bin[p] = (unsigned short)(b + 3); }
    }
    __syncthreads();

    // ---- Phase 3.5: per-class metadata, one thread per class (hoisted out
    //      of the hot gather loop). ----
    if (tid < NCLS) {
        if (s_hist[tid]) g_present[tid] = 1u;     // racing identical stores: fine
        unsigned kc = s_cur[tid] - s_off[tid];
        if (kc) atomicAdd(&g_counts[tid], (float)kc);
    }
    __syncthreads();

    // ---- Phase 4: one warp per class (strided). Pure unroll-8 main loop
    //      (no clamps, no weight FMAs) + clamped-4 tail; then one
    //      red.global.add.v4.f32 per (CTA, class). ----
    const float4* __restrict__ x4 = (const float4*)x;
    for (int c = (int)wid; c < NCLS; c += 32) {
        unsigned base = s_off[c];
        unsigned k    = s_cur[c] - base;    // masked count
        if (!k) continue;

        float4 a0 = make_float4(0.f, 0.f, 0.f, 0.f);
        float4 a1 = make_float4(0.f, 0.f, 0.f, 0.f);

        unsigned j = 0;
        // Main loop: 8 independent 512B loads in flight, zero clamp overhead.
        for (; j + 8 <= k; j += 8) {
            float4 vv[8];
            #pragma unroll
            for (int t = 0; t < 8; t++) {
                int ri = row0 + (int)s_bin[base + j + (unsigned)t];
                vv[t] = __ldcs(&x4[(size_t)ri * 32 + lane]);
            }
            #pragma unroll
            for (int t = 0; t < 8; t += 2) {
                a0.x += vv[t].x;   a0.y += vv[t].y;   a0.z += vv[t].z;   a0.w += vv[t].w;
                a1.x += vv[t+1].x; a1.y += vv[t+1].y; a1.z += vv[t+1].z; a1.w += vv[t+1].w;
            }
        }
        // Clamped-4 tail (covers remainder 1..7 in one or two batches, MLP-4).
        if (j < k) {
            unsigned klast = k - 1;
            for (; j < k; j += 4) {
                unsigned j1 = min(j + 1, klast);
                unsigned j2 = min(j + 2, klast);
                unsigned j3 = min(j + 3, klast);
                float w1 = (j + 1 <= klast) ? 1.f : 0.f;
                float w2 = (j + 2 <= klast) ? 1.f : 0.f;
                float w3 = (j + 3 <= klast) ? 1.f : 0.f;
                int i0 = row0 + (int)s_bin[base + j];
                int i1 = row0 + (int)s_bin[base + j1];
                int i2 = row0 + (int)s_bin[base + j2];
                int i3 = row0 + (int)s_bin[base + j3];
                float4 v0 = __ldcs(&x4[(size_t)i0 * 32 + lane]);
                float4 v1 = __ldcs(&x4[(size_t)i1 * 32 + lane]);
                float4 v2 = __ldcs(&x4[(size_t)i2 * 32 + lane]);
                float4 v3 = __ldcs(&x4[(size_t)i3 * 32 + lane]);
                a0.x += v0.x;      a0.y += v0.y;      a0.z += v0.z;      a0.w += v0.w;
                a1.x += v1.x * w1; a1.y += v1.y * w1; a1.z += v1.z * w1; a1.w += v1.w * w1;
                a0.x += v2.x * w2; a0.y += v2.y * w2; a0.z += v2.z * w2; a0.w += v2.w * w2;
                a1.x += v3.x * w3; a1.y += v3.y * w3; a1.z += v3.z * w3; a1.w += v3.w * w3;
            }
        }
        a0.x += a1.x; a0.y += a1.y; a0.z += a1.z; a0.w += a1.w;

        float* dst = &g_sums[c * DIM + lane * 4];
        asm volatile("red.global.add.v4.f32 [%0], {%1, %2, %3, %4};"
                     :: "l"(dst), "f"(a0.x), "f"(a0.y), "f"(a0.z), "f"(a0.w)
                     : "memory");
    }
}

// One thread per float4 (32000 threads). Branchless: all input loads issued
// independently (MLP 4), select at the end.
__global__ void finalize_kernel(const float4* __restrict__ centroids,
                                float4* __restrict__ out)
{
    int idx = blockIdx.x * blockDim.x + threadIdx.x;   // float4 index
    if (idx >= NCLS * DIM / 4) return;
    int c = idx >> 5;                                   // 32 float4 per class row

    float4   cent = centroids[idx];
    float4   s    = ((const float4*)g_sums)[idx];
    float    cnt  = g_counts[c];
    unsigned pres = g_present[c];

    float invn = DECAY / fmaxf(cnt, 1.0f);
    float keep = 1.0f - DECAY;
    float4 ema;
    ema.x = s.x * invn + keep * cent.x;
    ema.y = s.y * invn + keep * cent.y;
    ema.z = s.z * invn + keep * cent.z;
    ema.w = s.w * invn + keep * cent.w;

    out[idx] = pres ? ema : cent;

    // Restore the zero-invariant for the next call / graph replay.
    ((float4*)g_sums)[idx] = make_float4(0.f, 0.f, 0.f, 0.f);
    if (idx < NCLS) { g_counts[idx] = 0.0f; g_present[idx] = 0u; }
}

extern "C" void kernel_launch(void* const* d_in, const int* in_sizes, int n_in,
                              void* d_out, int out_size)
{
    const float* x         = (const float*)d_in[0];
    const int*   y         = (const int*)d_in[1];
    const int*   mask      = (const int*)d_in[2];
    const float* centroids = (const float*)d_in[3];
    float*       out       = (float*)d_out;

    accum_kernel<<<NBLK, THREADS>>>(x, y, mask);
    finalize_kernel<<<(NCLS * DIM / 4 + 255) / 256, 256>>>(
        (const float4*)centroids, (float4*)out);
}